// round 7
// baseline (speedup 1.0000x reference)
#include <cuda_runtime.h>
#include <cstdint>

#define LROW 4096
#define THREADS 256
#define VPT (LROW / 4 / THREADS)   // 16B quads per thread = 4
#define FULLW 0xffffffffu

// ---------------------------------------------------------------------------
// SubsetSampler, exploiting tail-padding structure of the mask.
// mask row = [0]*len ++ [1]*(L-len)  (monotone), len in [1, L].
// cutoff = min(ceil(float(len)*0.7f), L-1) <= len  =>  new_mask[j] = (j>=cutoff).
//
// 2-round probe:
//   round 1: 256 threads probe m[16*tid] -> len in (base, base+16]
//   round 2: warp 0 probes m[base+1 .. base+15] -> exact len
// Mask quads certain after round 1 are written concurrently with round 2;
// only the <=5 boundary quads wait for the exact cutoff.
// ---------------------------------------------------------------------------
__global__ void __launch_bounds__(THREADS)
subset_kernel(const float4* __restrict__ x,
              const int* __restrict__ mask,
              float4* __restrict__ out_x,
              float4* __restrict__ out_m) {
    const int row = blockIdx.x;
    const int tid = threadIdx.x;
    const int lane = tid & 31;
    const int wid  = tid >> 5;
    const size_t rbase = (size_t)row * (LROW / 4);   // in 16B quads
    const int* m = mask + (size_t)row * LROW;

    __shared__ unsigned s_ball[THREADS / 32];
    __shared__ int s_cutoff;

    // ---- round-1 probe load first (starts the dependent chain ASAP) ----
    const int probe1 = m[16 * tid];                  // tid=0 -> m[0]=0 always

    // ---- x row loads (in flight under the ballot/barrier) ----
    float4 xv[VPT];
#pragma unroll
    for (int i = 0; i < VPT; i++)
        xv[i] = x[rbase + tid + i * THREADS];

    const unsigned wb = __ballot_sync(FULLW, probe1 != 0);
    if (lane == 0) s_ball[wid] = wb;
    __syncthreads();

    // every thread derives base from the 8 ballot words (uniform)
    int f = -1;
#pragma unroll
    for (int w = 0; w < THREADS / 32; w++) {
        const unsigned bw = s_ball[w];
        if (f < 0 && bw) f = 32 * w + __ffs(bw) - 1;
    }
    const int base = (f < 0) ? (LROW - 16) : 16 * (f - 1);  // len in (base, base+16]

    // cutoff bounds from the 16-wide len window (f32 math, monotone)
    const int cut_lo = (int)ceilf((float)(base + 1) * 0.7f);
    int cut_hi = (int)ceilf((float)(base + 16) * 0.7f);
    if (cut_hi > LROW - 1) cut_hi = LROW - 1;

    // ---- round 2: warp 0 resolves exact len while others stream ----
    if (wid == 0) {
        bool hit = false;
        if (lane >= 1 && lane < 16) hit = (m[base + lane] != 0);
        const unsigned b2 = __ballot_sync(FULLW, hit);
        if (lane == 0) {
            const int len = b2 ? (base + __ffs(b2) - 1) : (base + 16);
            int c = (int)ceilf((float)len * 0.7f);   // f32 math like reference
            if (c > LROW - 1) c = LROW - 1;
            s_cutoff = c;
        }
    }

    // ---- x stores + certain mask quads (no dependence on round 2) ----
    bool defer[VPT];
#pragma unroll
    for (int i = 0; i < VPT; i++) {
        const int idx = tid + i * THREADS;
        out_x[rbase + idx] = xv[i];

        const int j = idx * 4;
        if (j + 3 < cut_lo) {                 // entirely below any cutoff
            out_m[rbase + idx] = make_float4(0.f, 0.f, 0.f, 0.f);
            defer[i] = false;
        } else if (j >= cut_hi) {             // entirely at/above any cutoff
            out_m[rbase + idx] = make_float4(1.f, 1.f, 1.f, 1.f);
            defer[i] = false;
        } else {
            defer[i] = true;                  // boundary quad, needs exact cutoff
        }
    }

    __syncthreads();
    const int cutoff = s_cutoff;

    // ---- boundary quads (<= ~5 per row) ----
#pragma unroll
    for (int i = 0; i < VPT; i++) {
        if (defer[i]) {
            const int idx = tid + i * THREADS;
            const int j = idx * 4;
            float4 o;
            o.x = (j + 0 >= cutoff) ? 1.0f : 0.0f;
            o.y = (j + 1 >= cutoff) ? 1.0f : 0.0f;
            o.z = (j + 2 >= cutoff) ? 1.0f : 0.0f;
            o.w = (j + 3 >= cutoff) ? 1.0f : 0.0f;
            out_m[rbase + idx] = o;
        }
    }
}

extern "C" void kernel_launch(void* const* d_in, const int* in_sizes, int n_in,
                              void* d_out, int out_size) {
    const float* x    = (const float*)d_in[0];
    const int*   mask = (const int*)d_in[1];        // bool transported as int32
    const long long n = (long long)in_sizes[0];     // B*L elements of x
    const int B = (int)(n / LROW);

    float* out_x = (float*)d_out;
    float* out_m = out_x + n;                        // [x | new_mask]
    subset_kernel<<<B, THREADS>>>((const float4*)x, mask,
                                  (float4*)out_x, (float4*)out_m);
}

// round 8
// speedup vs baseline: 1.1823x; 1.1823x over previous
#include <cuda_runtime.h>
#include <cstdint>

#define LROW 4096
#define THREADS 256
#define VPT (LROW / 4 / THREADS)   // 16B quads per thread = 4
#define FULLW 0xffffffffu

// ---------------------------------------------------------------------------
// SubsetSampler, exploiting tail-padding structure of the mask.
// mask row = [0]*len ++ [1]*(L-len)  (monotone), len in [1, L].
// cutoff = min(ceil(float(len)*0.7f), L-1) <= len  =>  new_mask[j] = (j>=cutoff).
//
// Every warp independently runs a narrow 3-round ballot search:
//   round 1: 32 probes at stride 128 (32 sectors, ~1KB/row; dedup across warps)
//   round 2: 15 probes at stride 4 inside the 128-window
//   round 3: 3 probes at stride 1
// No smem, no __syncthreads. After round 1 the cutoff window is <=90 wide,
// so ~97% of mask quads store immediately; only boundary quads wait on the
// full probe chain.
// ---------------------------------------------------------------------------
__global__ void __launch_bounds__(THREADS)
subset_kernel(const float4* __restrict__ x,
              const int* __restrict__ mask,
              float4* __restrict__ out_x,
              float4* __restrict__ out_m) {
    const int row = blockIdx.x;
    const int tid = threadIdx.x;
    const int lane = tid & 31;
    const size_t rbase = (size_t)row * (LROW / 4);   // in 16B quads
    const int* m = mask + (size_t)row * LROW;

    // ---- round-1 probe first (starts the dependent chain ASAP) ----
    const int probe1 = m[128 * lane];                // lane 0 -> m[0] = 0 always

    // ---- x row loads (fill the pipe while the probe is in flight) ----
    float4 xv[VPT];
#pragma unroll
    for (int i = 0; i < VPT; i++)
        xv[i] = x[rbase + tid + i * THREADS];

    // round 1 resolve: len in (base, base+128]
    const unsigned b1 = __ballot_sync(FULLW, probe1 != 0);
    const int base = b1 ? 128 * (__ffs(b1) - 2 + 1) - 128  // 128*(fs-1)
                        : (LROW - 128);

    // cutoff window bounds (f32 math, monotone in len)
    const int cut_lo = (int)ceilf((float)(base + 1) * 0.7f);
    int cut_hi = (int)ceilf((float)(base + 128) * 0.7f);
    if (cut_hi > LROW - 1) cut_hi = LROW - 1;

    // ---- round 2: 15 probes at stride 4 (all warps, same addrs -> dedup) ----
    int p2 = base + 4 * (lane + 1);
    if (p2 > LROW - 1) p2 = LROW - 1;
    const bool hit2 = (lane < 32) && (m[p2] != 0);   // lane31 probes base+128
    const unsigned b2 = __ballot_sync(FULLW, hit2);

    // ---- x stores + certain mask quads (independent of rounds 2/3) ----
    bool defer[VPT];
#pragma unroll
    for (int i = 0; i < VPT; i++) {
        const int idx = tid + i * THREADS;
        out_x[rbase + idx] = xv[i];

        const int j = idx * 4;
        if (j + 3 < cut_lo) {
            out_m[rbase + idx] = make_float4(0.f, 0.f, 0.f, 0.f);
            defer[i] = false;
        } else if (j >= cut_hi) {
            out_m[rbase + idx] = make_float4(1.f, 1.f, 1.f, 1.f);
            defer[i] = false;
        } else {
            defer[i] = true;                  // boundary quad
        }
    }

    // ---- rounds 2/3 resolve exact len (per-warp, uniform result) ----
    int len;
    if (b2 == 0) {
        len = LROW;                           // whole row False (only b1==0 path)
    } else {
        const int base2 = base + 4 * (__ffs(b2) - 1);   // len in (base2, base2+4]
        int p3 = base2 + lane;
        if (p3 > LROW - 1) p3 = LROW - 1;
        const bool hit3 = (lane >= 1 && lane < 4) && (m[p3] != 0);
        const unsigned b3 = __ballot_sync(FULLW, hit3);
        len = b3 ? (base2 + __ffs(b3) - 1) : (base2 + 4);
    }
    int cutoff = (int)ceilf((float)len * 0.7f);       // f32 math like reference
    if (cutoff > LROW - 1) cutoff = LROW - 1;

    // ---- boundary quads ----
#pragma unroll
    for (int i = 0; i < VPT; i++) {
        if (defer[i]) {
            const int idx = tid + i * THREADS;
            const int j = idx * 4;
            float4 o;
            o.x = (j + 0 >= cutoff) ? 1.0f : 0.0f;
            o.y = (j + 1 >= cutoff) ? 1.0f : 0.0f;
            o.z = (j + 2 >= cutoff) ? 1.0f : 0.0f;
            o.w = (j + 3 >= cutoff) ? 1.0f : 0.0f;
            out_m[rbase + idx] = o;
        }
    }
}

extern "C" void kernel_launch(void* const* d_in, const int* in_sizes, int n_in,
                              void* d_out, int out_size) {
    const float* x    = (const float*)d_in[0];
    const int*   mask = (const int*)d_in[1];        // bool transported as int32
    const long long n = (long long)in_sizes[0];     // B*L elements of x
    const int B = (int)(n / LROW);

    float* out_x = (float*)d_out;
    float* out_m = out_x + n;                        // [x | new_mask]
    subset_kernel<<<B, THREADS>>>((const float4*)x, mask,
                                  (float4*)out_x, (float4*)out_m);
}